// round 7
// baseline (speedup 1.0000x reference)
#include <cuda_runtime.h>
#include <cuda_bf16.h>

// Problem constants (fixed by setup_inputs):
//   encoder_output: (B=32, L_ENC=512, E=256) float32
//   durations:      (B=32, L_ENC=512) int32, values in [0, 8)
//   output:         (B=32, L_DEC=2048, E=256) float32
//
// out[b, d, :] = enc[b, l, :] where excl_cs[l] <= d < incl_cs[l]; 0 past end.

#define B_SZ    32
#define L_ENC   512
#define L_DEC   2048
#define E_DIM   256
#define E_VEC   (E_DIM / 4)            // 64 float4 per row
#define DEC_PER_THREAD (L_DEC / L_ENC) // 4
#define N_ROWS  (B_SZ * L_DEC)         // 65536 decoder rows
#define ROWS_PER_GROUP 8
#define ROWS_PER_BLOCK 64              // 8 groups x 8 rows

// Per-decoder-position source row (absolute: b*L_ENC + l), or -1 for padding.
__device__ int g_src[N_ROWS];

// ---------------------------------------------------------------------------
// Kernel A: per-batch scan of durations (warp-shuffle based) + scatter of
// source indices. One block per batch, 512 threads (16 warps).
// ---------------------------------------------------------------------------
__global__ void lr_index_kernel(const int* __restrict__ dur)
{
    __shared__ int warp_sums[16];
    const int b    = blockIdx.x;
    const int t    = threadIdx.x;
    const int wid  = t >> 5;
    const int lane = t & 31;

    const int my_dur = dur[b * L_ENC + t];

    // Inclusive warp scan.
    int v = my_dur;
    #pragma unroll
    for (int off = 1; off < 32; off <<= 1) {
        int u = __shfl_up_sync(0xffffffffu, v, off);
        if (lane >= off) v += u;
    }
    if (lane == 31) warp_sums[wid] = v;
    __syncthreads();

    // Warp 0 scans the 16 warp sums (exclusive result back to smem).
    if (wid == 0 && lane < 16) {
        int ws = warp_sums[lane];
        #pragma unroll
        for (int off = 1; off < 16; off <<= 1) {
            int u = __shfl_up_sync(0x0000ffffu, ws, off);
            if (lane >= off) ws += u;
        }
        warp_sums[lane] = ws - warp_sums[lane];   // exclusive prefix
    }
    __syncthreads();

    const int incl = v + warp_sums[wid];
    const int excl = incl - my_dur;

    int* src_b = g_src + b * L_DEC;

    // Pre-fill with -1 (padding sentinel).
    #pragma unroll
    for (int i = 0; i < DEC_PER_THREAD; ++i)
        src_b[t * DEC_PER_THREAD + i] = -1;
    __syncthreads();

    // Scatter: decoder positions [excl, min(incl, L_DEC)) map to encoder row t.
    const int hi = incl < L_DEC ? incl : L_DEC;
    const int row = b * L_ENC + t;
    for (int d = excl; d < hi; ++d)
        src_b[d] = row;
}

// ---------------------------------------------------------------------------
// Kernel B: gather-copy, locality-tiled. Block covers 64 CONSECUTIVE decoder
// rows (all within one batch since L_DEC % 64 == 0): 8 groups of 64 lanes,
// each group copies 8 consecutive rows. Consecutive rows usually share the
// same encoder source row (avg duration ~3.5) -> enc loads hit L1.
// Phase-batched (idx x8, load x8, store x8) for MLP=8.
// ---------------------------------------------------------------------------
__global__ void __launch_bounds__(512)
lr_copy_kernel(const float4* __restrict__ enc, float4* __restrict__ out)
{
    const int group = threadIdx.x >> 6;          // 0..7
    const int lane  = threadIdx.x & 63;          // 0..63
    const int row0  = blockIdx.x * ROWS_PER_BLOCK + group * ROWS_PER_GROUP;

    // Phase 1: batch index loads (broadcast within the 64-lane group).
    int src[ROWS_PER_GROUP];
    #pragma unroll
    for (int j = 0; j < ROWS_PER_GROUP; ++j)
        src[j] = g_src[row0 + j];

    // Phase 2: batch data loads (unconditional via clamp; select after).
    float4 v[ROWS_PER_GROUP];
    #pragma unroll
    for (int j = 0; j < ROWS_PER_GROUP; ++j) {
        const int safe = src[j] >= 0 ? src[j] : 0;
        v[j] = enc[(long)safe * E_VEC + lane];
    }

    // Phase 3: select zeros for padding rows, store 8 consecutive rows.
    #pragma unroll
    for (int j = 0; j < ROWS_PER_GROUP; ++j) {
        if (src[j] < 0) v[j] = make_float4(0.f, 0.f, 0.f, 0.f);
        out[(long)(row0 + j) * E_VEC + lane] = v[j];
    }
}

// ---------------------------------------------------------------------------
extern "C" void kernel_launch(void* const* d_in, const int* in_sizes, int n_in,
                              void* d_out, int out_size)
{
    const float* enc = (const float*)d_in[0];     // (B, L_ENC, E)
    const int*   dur = (const int*)d_in[1];       // (B, L_ENC) int32
    (void)in_sizes; (void)n_in; (void)out_size;

    lr_index_kernel<<<B_SZ, L_ENC>>>(dur);

    lr_copy_kernel<<<N_ROWS / ROWS_PER_BLOCK, 512>>>((const float4*)enc,
                                                     (float4*)d_out);
}

// round 8
// speedup vs baseline: 1.0019x; 1.0019x over previous
#include <cuda_runtime.h>
#include <cuda_bf16.h>

// Problem constants (fixed by setup_inputs):
//   encoder_output: (B=32, L_ENC=512, E=256) float32
//   durations:      (B=32, L_ENC=512) int32, values in [0, 8)
//   output:         (B=32, L_DEC=2048, E=256) float32
//
// out[b, d, :] = enc[b, l, :] where excl_cs[l] <= d < incl_cs[l]; 0 past end.

#define B_SZ    32
#define L_ENC   512
#define L_DEC   2048
#define E_DIM   256
#define E_VEC   (E_DIM / 4)            // 64 float4 per row
#define DEC_PER_THREAD (L_DEC / L_ENC) // 4
#define N_ROWS  (B_SZ * L_DEC)         // 65536 decoder rows
#define ROWS_PER_GROUP 8
#define ROWS_PER_BLOCK 64              // 8 groups x 8 rows

// Per-decoder-position source row (absolute: b*L_ENC + l), or -1 for padding.
__device__ int g_src[N_ROWS];

// ---------------------------------------------------------------------------
// Kernel A: per-batch scan of durations (warp-shuffle based) + scatter of
// source indices. One block per batch, 512 threads (16 warps).
// ---------------------------------------------------------------------------
__global__ void lr_index_kernel(const int* __restrict__ dur)
{
    __shared__ int warp_sums[16];
    const int b    = blockIdx.x;
    const int t    = threadIdx.x;
    const int wid  = t >> 5;
    const int lane = t & 31;

    const int my_dur = dur[b * L_ENC + t];

    // Inclusive warp scan.
    int v = my_dur;
    #pragma unroll
    for (int off = 1; off < 32; off <<= 1) {
        int u = __shfl_up_sync(0xffffffffu, v, off);
        if (lane >= off) v += u;
    }
    if (lane == 31) warp_sums[wid] = v;
    __syncthreads();

    // Warp 0 scans the 16 warp sums (exclusive result back to smem).
    if (wid == 0 && lane < 16) {
        int ws = warp_sums[lane];
        #pragma unroll
        for (int off = 1; off < 16; off <<= 1) {
            int u = __shfl_up_sync(0x0000ffffu, ws, off);
            if (lane >= off) ws += u;
        }
        warp_sums[lane] = ws - warp_sums[lane];   // exclusive prefix
    }
    __syncthreads();

    const int incl = v + warp_sums[wid];
    const int excl = incl - my_dur;

    int* src_b = g_src + b * L_DEC;

    // Pre-fill with -1 (padding sentinel).
    #pragma unroll
    for (int i = 0; i < DEC_PER_THREAD; ++i)
        src_b[t * DEC_PER_THREAD + i] = -1;
    __syncthreads();

    // Scatter: decoder positions [excl, min(incl, L_DEC)) map to encoder row t.
    const int hi = incl < L_DEC ? incl : L_DEC;
    const int row = b * L_ENC + t;
    for (int d = excl; d < hi; ++d)
        src_b[d] = row;
}

// ---------------------------------------------------------------------------
// Kernel B: gather-copy, locality-tiled, with COMPILER-PROOF MLP=8.
// Block covers 64 consecutive decoder rows: 8 groups of 64 lanes, each group
// copies 8 consecutive rows (consecutive rows usually share the encoder
// source row -> L1 hits). The 8 row-loads are issued via asm volatile
// ld.global.nc.v4.f32 so ptxas cannot sink them into the store loop:
// all 8 are in flight before the first store.
// ---------------------------------------------------------------------------
__global__ void __launch_bounds__(512)
lr_copy_kernel(const float4* __restrict__ enc, float4* __restrict__ out)
{
    __shared__ int s_src[ROWS_PER_BLOCK];

    const int t     = threadIdx.x;
    const int group = t >> 6;                    // 0..7
    const int lane  = t & 63;                    // 0..63
    const int brow0 = blockIdx.x * ROWS_PER_BLOCK;

    // Stage this block's 64 source indices in shared memory.
    if (t < ROWS_PER_BLOCK)
        s_src[t] = g_src[brow0 + t];
    __syncthreads();

    const int row0 = group * ROWS_PER_GROUP;     // local row base

    int src[ROWS_PER_GROUP];
    #pragma unroll
    for (int j = 0; j < ROWS_PER_GROUP; ++j)
        src[j] = s_src[row0 + j];                // broadcast LDS

    // Batched loads: asm volatile keeps all 8 LDGs issued before any store.
    float4 v[ROWS_PER_GROUP];
    #pragma unroll
    for (int j = 0; j < ROWS_PER_GROUP; ++j) {
        const int safe = src[j] >= 0 ? src[j] : 0;
        const float4* p = enc + (long)safe * E_VEC + lane;
        asm volatile("ld.global.nc.v4.f32 {%0, %1, %2, %3}, [%4];"
                     : "=f"(v[j].x), "=f"(v[j].y), "=f"(v[j].z), "=f"(v[j].w)
                     : "l"(p));
    }

    // Select zeros for padding rows, store 8 consecutive rows.
    #pragma unroll
    for (int j = 0; j < ROWS_PER_GROUP; ++j) {
        if (src[j] < 0) v[j] = make_float4(0.f, 0.f, 0.f, 0.f);
        out[(long)(brow0 + row0 + j) * E_VEC + lane] = v[j];
    }
}

// ---------------------------------------------------------------------------
extern "C" void kernel_launch(void* const* d_in, const int* in_sizes, int n_in,
                              void* d_out, int out_size)
{
    const float* enc = (const float*)d_in[0];     // (B, L_ENC, E)
    const int*   dur = (const int*)d_in[1];       // (B, L_ENC) int32
    (void)in_sizes; (void)n_in; (void)out_size;

    lr_index_kernel<<<B_SZ, L_ENC>>>(dur);

    lr_copy_kernel<<<N_ROWS / ROWS_PER_BLOCK, 512>>>((const float4*)enc,
                                                     (float4*)d_out);
}